// round 11
// baseline (speedup 1.0000x reference)
#include <cuda_runtime.h>
#include <math.h>
#include <stdint.h>

// Fixed problem shape: x = float32[32,3,512,512], sign = scalar int, out = float32[1]
#define N_IMG      32
#define PLANE      (512 * 512)        // 262144 pixels per channel
#define BINS       256
#define HB_THREADS 128                // threads per block
#define BIMG       32                 // blocks per image -> 1024 blocks ~ one wave @7/SM
#define NBLOCKS    (N_IMG * BIMG)
#define PPB        (PLANE / BIMG)     // 8192 pixels per block
#define F4_PER_BLK (PPB / 4)          // 2048 float4 per channel per block
#define ITERS      (F4_PER_BLK / HB_THREADS)  // 16 iterations per thread (64 px/thread)

// Global per-image histograms + arrival ticket. Zero-initialized at module
// load; the last block re-zeroes g_cnt and resets g_arrive after use, so
// every launch / graph replay observes zeros. Deterministic.
__device__ unsigned g_cnt[N_IMG * BINS];
__device__ unsigned g_arrive;

// ---------------------------------------------------------------------------
// Binning (validated rel_err 7.2e-6, gate 1e-3):
//   y = 0.257 r + 0.564 g + 0.098 b + 0.0625 in [0.0625, 0.982)
//   idx = round_half_even(255 y) in [16,250] via magic-number fma; the ref's
//   strict window only drops exact round-half ties. Count every pixel.
// Per-thread private u8 histogram, conflict-free layout:
//   byte addr = (idx>>2)*512 + tid*4 + (idx&3)
//   -> 32-bit word index = (idx>>2)*128 + tid -> bank = tid % 32 always.
// 64 px/thread -> max byte count 64.
// ---------------------------------------------------------------------------
__device__ __forceinline__ void ie_bump(float a, float b, float c,
                                        unsigned char* hbase) {
    const float MAGIC = 12582912.0f;               // 1.5 * 2^23
    float y = 0.257f * a + 0.564f * b + 0.098f * c + 0.0625f;
    float t = __fmaf_rn(y, 255.0f, MAGIC);         // RN -> half-to-even
    int   idx = __float_as_int(t) & 0xFF;          // idx in [16,250]
    int addr = ((idx >> 2) * (HB_THREADS * 4)) + (idx & 3);
    hbase[addr] = (unsigned char)(hbase[addr] + 1);
}

__global__ void __launch_bounds__(HB_THREADS, 7)
ie_fused_kernel(const float* __restrict__ x,
                const void* __restrict__ signp,
                float* __restrict__ out) {
    __shared__ unsigned char h[64 * HB_THREADS * 4];   // 32 KB
    unsigned*  h32  = reinterpret_cast<unsigned*>(h);
    uint4*     h128 = reinterpret_cast<uint4*>(h);

    const int tid = threadIdx.x;
    const int bi  = blockIdx.x;   // chunk within image, 0..BIMG-1
    const int img = blockIdx.y;   // image, 0..31
    unsigned char* hbase = h + (tid << 2);   // per-thread column

    // zero private histograms (2048 uint4 / 128 threads = 16 each)
    #pragma unroll
    for (int i = 0; i < 16; i++)
        h128[i * HB_THREADS + tid] = make_uint4(0u, 0u, 0u, 0u);
    __syncthreads();

    const float* base = x + (size_t)img * 3 * PLANE;
    const int chunk = bi * PPB;
    const float4* r4 = reinterpret_cast<const float4*>(base + chunk) + tid;
    const float4* g4 = reinterpret_cast<const float4*>(base + PLANE + chunk) + tid;
    const float4* b4 = reinterpret_cast<const float4*>(base + 2 * PLANE + chunk) + tid;

    // Software pipeline, distance 2: six LDG.128 (24 cache lines) in flight
    // per warp while executing bumps two iterations behind — covers the
    // ~250-400 cyc L2/DRAM latency that distance-1 (R10) only half-hid.
    float4 r0 = __ldg(r4), g0 = __ldg(g4), b0 = __ldg(b4);
    float4 r1 = __ldg(r4 + HB_THREADS);
    float4 g1 = __ldg(g4 + HB_THREADS);
    float4 b1 = __ldg(b4 + HB_THREADS);

    #pragma unroll
    for (int k = 0; k < ITERS - 2; k++) {
        // issue loads for k+2 (unpredicated in the steady state)
        float4 rn = __ldg(r4 + (k + 2) * HB_THREADS);
        float4 gn = __ldg(g4 + (k + 2) * HB_THREADS);
        float4 bn = __ldg(b4 + (k + 2) * HB_THREADS);
        // consume iteration k
        ie_bump(r0.x, g0.x, b0.x, hbase);
        ie_bump(r0.y, g0.y, b0.y, hbase);
        ie_bump(r0.z, g0.z, b0.z, hbase);
        ie_bump(r0.w, g0.w, b0.w, hbase);
        r0 = r1; g0 = g1; b0 = b1;
        r1 = rn; g1 = gn; b1 = bn;
    }
    // epilogue: two remaining iterations
    ie_bump(r0.x, g0.x, b0.x, hbase);
    ie_bump(r0.y, g0.y, b0.y, hbase);
    ie_bump(r0.z, g0.z, b0.z, hbase);
    ie_bump(r0.w, g0.w, b0.w, hbase);
    ie_bump(r1.x, g1.x, b1.x, hbase);
    ie_bump(r1.y, g1.y, b1.y, hbase);
    ie_bump(r1.z, g1.z, b1.z, hbase);
    ie_bump(r1.w, g1.w, b1.w, hbase);
    __syncthreads();

    // Flush: thread t handles bin-group g = t&63 (bins 4g..4g+3) over half
    // the 128 copies (hh = t>>6). Rotated start keeps banks distinct.
    // Bytes <= 64, so pairwise word-add is carry-free (<=128); SIMD halfword
    // accumulate (max 32*128=4096 < 2^16).
    __shared__ unsigned partial[64][4];
    {
        const int g  = tid & 63;
        const int hh = tid >> 6;
        const unsigned* row = h32 + g * HB_THREADS;
        unsigned a02 = 0, a13 = 0;
        #pragma unroll 8
        for (int k = 0; k < 32; k++) {
            unsigned w0 = row[(g + hh * 64 + 2 * k)     & (HB_THREADS - 1)];
            unsigned w1 = row[(g + hh * 64 + 2 * k + 1) & (HB_THREADS - 1)];
            unsigned w2 = w0 + w1;                 // carry-free: bytes <= 128
            a02 += w2 & 0x00FF00FFu;
            a13 += (w2 >> 8) & 0x00FF00FFu;
        }
        if (hh) {
            partial[g][0] = a02 & 0xFFFFu;  partial[g][1] = a13 & 0xFFFFu;
            partial[g][2] = a02 >> 16;      partial[g][3] = a13 >> 16;
        }
        __syncthreads();
        if (!hh) {
            unsigned* dst = g_cnt + img * BINS + g * 4;
            atomicAdd(dst + 0, (a02 & 0xFFFFu) + partial[g][0]);
            atomicAdd(dst + 1, (a13 & 0xFFFFu) + partial[g][1]);
            atomicAdd(dst + 2, (a02 >> 16)     + partial[g][2]);
            atomicAdd(dst + 3, (a13 >> 16)     + partial[g][3]);
        }
    }

    // ---- grid-wide completion: last arriving block computes the entropy ----
    __threadfence();                    // make our g_cnt REDs globally visible
    __syncthreads();
    __shared__ unsigned islast;
    if (tid == 0)
        islast = (atomicAdd(&g_arrive, 1u) == (unsigned)(NBLOCKS - 1));
    __syncthreads();
    if (!islast) return;

    __threadfence();                    // acquire side of the ticket
    // Entropy: flat sum over all 8192 (img,bin) pairs of -H*log2(H),
    // H = cnt/N. Zero g_cnt for the next replay.
    const float invN = 1.0f / (float)PLANE;
    float s = 0.0f;
    #pragma unroll
    for (int j = 0; j < (N_IMG * BINS) / HB_THREADS; j++) {
        int p = j * HB_THREADS + tid;
        unsigned c = *(volatile unsigned*)&g_cnt[p];
        g_cnt[p] = 0u;
        if (c) {
            float H = (float)c * invN;
            s -= H * __log2f(H);
        }
    }
    __shared__ float red[4];
    #pragma unroll
    for (int o = 16; o; o >>= 1) s += __shfl_xor_sync(0xFFFFFFFFu, s, o);
    if ((tid & 31) == 0) red[tid >> 5] = s;
    __syncthreads();
    if (tid == 0) {
        float e = red[0] + red[1] + red[2] + red[3];
        int iv = *(const int*)signp;
        float sv = (iv == 1 || iv == 0 || iv == -1) ? (float)iv
                                                    : __int_as_float(iv);
        out[0] = sv * e * (1.0f / (float)N_IMG);
        g_arrive = 0u;                  // reset ticket for next replay
    }
}

// ---------------------------------------------------------------------------
extern "C" void kernel_launch(void* const* d_in, const int* in_sizes, int n_in,
                              void* d_out, int out_size) {
    (void)in_sizes; (void)n_in; (void)out_size;
    const float* x = (const float*)d_in[0];
    dim3 grid(BIMG, N_IMG);
    ie_fused_kernel<<<grid, HB_THREADS>>>(x, d_in[1], (float*)d_out);
}